// round 15
// baseline (speedup 1.0000x reference)
#include <cuda_runtime.h>
#include <math.h>
#include <stdint.h>

#define NC 65
#define NG 22
#define MAXB 64
#define EPS 1e-8f
#define SUB 128                 // rows per subtile (one per quad)
#define NSUB 4
#define CHUNK (SUB * NSUB)      // 512 rows per block
#define THR 512                 // 4 threads per row
#define NW (THR / 32)           // 16 warps
#define FULL 0xffffffffu

// ---- constants derived from AA64 = 'FFLLSSSSYY**CC*WLLLLPPPPHHQQRRRRIIIMTTTTNNKKSSRRVVVVAAAADDEEGGGG'
__constant__ int c_gid[NC] = {
    0,
    6,6, 11,11, 17,17,17,17, 21,21, 1,1, 3,3, 1, 20,
    11,11,11,11, 14,14,14,14, 8,8, 15,15, 16,16,16,16,
    9,9,9, 12, 18,18,18,18, 13,13, 10,10, 17,17, 16,16,
    19,19,19,19, 2,2,2,2, 4,4, 5,5, 7,7,7,7};
__constant__ float c_nsyn[NC] = {
    0.f,
    2,2, 6,6, 6,6,6,6, 2,2, 3,3, 2,2, 3, 1,
    6,6,6,6, 4,4,4,4, 2,2, 2,2, 6,6,6,6,
    3,3,3, 1, 4,4,4,4, 2,2, 2,2, 6,6, 6,6,
    4,4,4,4, 4,4,4,4, 2,2, 2,2, 4,4,4,4};

// ---- global scratch (zero at load; self-cleaned every run)
__device__ double g_lwp[MAXB], g_lwt[MAXB];
__device__ double g_gcs[MAXB], g_pps[MAXB];
__device__ int    g_maskc[MAXB];
__device__ int    g_cntp[MAXB][NC], g_cntt[MAXB][NC];
__device__ int    g_obsp[MAXB][NC], g_obst[MAXB][NC];
__device__ double g_ce_sum;
__device__ int    g_ce_cnt;
__device__ double g_rscu, g_cai, g_gc, g_dyn, g_str;
__device__ int    g_bdone[MAXB];
__device__ int    g_fin;

__device__ __forceinline__ void cp16(uint32_t saddr, const void* gptr) {
    asm volatile("cp.async.cg.shared.global [%0], [%1], 16;" :: "r"(saddr), "l"(gptr));
}
__device__ __forceinline__ void cp_commit() { asm volatile("cp.async.commit_group;"); }
template<int N> __device__ __forceinline__ void cp_wait() {
    asm volatile("cp.async.wait_group %0;" :: "n"(N));
}

// ------------- Single kernel: quad-per-row main pass + ticket epilogues -------------
__global__ void __launch_bounds__(THR) mainK(
    const float* __restrict__ logits, const float* __restrict__ wmat,
    const float* __restrict__ refd,
    const float* __restrict__ gc,     const float* __restrict__ pause,
    const float* __restrict__ mfe,
    const int* __restrict__ tgt,      const int* __restrict__ aa,
    const int* __restrict__ species,  const unsigned char* __restrict__ mask,
    float* __restrict__ out, int L, int B)
{
    const int b    = blockIdx.y;
    const int tid  = threadIdx.x;
    const int wid  = tid >> 5, lane = tid & 31;
    const int qrow = tid >> 2;          // 0..127: row within subtile
    const int q    = tid & 3;           // lane within quad
    const int nblk = gridDim.x;

    extern __shared__ float smem[];
    float* s_buf  = smem;                    // 2 * SUB * NC floats (ping-pong)
    float* s_logw = smem + 2 * SUB * NC;     // NC floats

    __shared__ int   s_cntp[NC], s_cntt[NC], s_obsp[NC], s_obst[NC];
    __shared__ float r_ce[NW], r_lwp[NW], r_lwt[NW], r_gc[NW], r_pp[NW];
    __shared__ int   r_cec[NW], r_mk[NW];
    // epilogue shared
    __shared__ float e_gsp[NG], e_gst[NG];
    __shared__ float e_sp, e_st, e_kl;
    __shared__ int   s_rank, s_f;

    const size_t row0 = (size_t)b * L + (size_t)blockIdx.x * CHUNK;
    const uint32_t sbase = (uint32_t)__cvta_generic_to_shared(s_buf);
    const int V = SUB * NC / 4;              // 2080 float4 per subtile

    // prefetch subtile 0
    {
        const float4* g4 = (const float4*)(logits + row0 * NC);
        for (int v = tid; v < V; v += THR) cp16(sbase + v * 16, g4 + v);
        cp_commit();
    }

    if (tid < NC) {
        int sp = __ldg(species + b);
        s_logw[tid] = __logf(fmaxf(__ldg(wmat + sp * NC + tid), EPS));
        s_cntp[tid] = 0; s_cntt[tid] = 0; s_obsp[tid] = 0; s_obst[tid] = 0;
    }

    // gc / pause partial sums: this block covers CHUNK elements of each
    {
        float sg = __ldg(gc + row0 + tid);
        float sp = __ldg(pause + row0 + tid);
        #pragma unroll
        for (int o = 16; o; o >>= 1) {
            sg += __shfl_xor_sync(FULL, sg, o);
            sp += __shfl_xor_sync(FULL, sp, o);
        }
        if (lane == 0) { r_gc[wid] = sg; r_pp[wid] = sp; }
    }

    float ce_acc = 0.f, lwp_acc = 0.f, lwt_acc = 0.f;
    int   cec_acc = 0, mk_acc = 0;

    const int base = q ? (q * 16 + 1) : 0;   // chunks: [0,17) [17,33) [33,49) [49,65)

    for (int s = 0; s < NSUB; ++s) {
        if (s + 1 < NSUB) {
            const float4* g4 = (const float4*)(logits + (row0 + (size_t)(s + 1) * SUB) * NC);
            uint32_t dst = sbase + ((s + 1) & 1) * (SUB * NC * 4);
            for (int v = tid; v < V; v += THR) cp16(dst + v * 16, g4 + v);
            cp_commit();
            cp_wait<1>();
        } else {
            cp_wait<0>();
        }
        __syncthreads();

        const float* row = s_buf + (s & 1) * (SUB * NC) + qrow * NC;
        const size_t r = row0 + (size_t)s * SUB + qrow;

        // pass 1: local max + argmax over this quad-lane's chunk
        float mx = row[base]; int am = base;
        #pragma unroll
        for (int i = 1; i < 16; ++i) {
            float v = row[base + i];
            if (v > mx) { mx = v; am = base + i; }
        }
        if (q == 0) { float v = row[16]; if (v > mx) { mx = v; am = 16; } }

        // combine across quad (first-index tie-break)
        #pragma unroll
        for (int o = 1; o <= 2; o <<= 1) {
            float omx = __shfl_xor_sync(FULL, mx, o);
            int   oam = __shfl_xor_sync(FULL, am, o);
            if (omx > mx || (omx == mx && oam < am)) { mx = omx; am = oam; }
        }

        // pass 2: sum of exps (re-read smem, keeps registers low)
        float e = 0.f;
        #pragma unroll
        for (int i = 0; i < 16; ++i) e += __expf(row[base + i] - mx);
        if (q == 0) e += __expf(row[16] - mx);
        #pragma unroll
        for (int o = 1; o <= 2; o <<= 1) e += __shfl_xor_sync(FULL, e, o);

        if (q == 0) {
            int t  = __ldg(tgt + r);
            int a  = __ldg(aa + r);
            int mk = __ldg(mask + r);

            float nll = mx + __logf(e) - row[t];
            if (t != 0) { ce_acc += nll; cec_acc++; }
            if (mk) {
                mk_acc++;
                lwp_acc += s_logw[am];
                lwt_acc += s_logw[t];
                if (am > 0) { atomicAdd(&s_cntp[am], 1); if (a > 2) s_obsp[am] = 1; }
                if (t  > 0) { atomicAdd(&s_cntt[t], 1);  if (a > 2) s_obst[t]  = 1; }
            }
        }
        __syncthreads();   // done reading this buffer before it is refilled
    }

    // block reduction of scalar accumulators (non-q0 lanes hold zeros)
    #pragma unroll
    for (int o = 16; o; o >>= 1) {
        ce_acc  += __shfl_xor_sync(FULL, ce_acc,  o);
        lwp_acc += __shfl_xor_sync(FULL, lwp_acc, o);
        lwt_acc += __shfl_xor_sync(FULL, lwt_acc, o);
        cec_acc += __shfl_xor_sync(FULL, cec_acc, o);
        mk_acc  += __shfl_xor_sync(FULL, mk_acc,  o);
    }
    if (lane == 0) {
        r_ce[wid] = ce_acc; r_lwp[wid] = lwp_acc; r_lwt[wid] = lwt_acc;
        r_cec[wid] = cec_acc; r_mk[wid] = mk_acc;
    }
    __syncthreads();

    if (tid < NC) {
        int cp = s_cntp[tid], ct = s_cntt[tid];
        if (cp) atomicAdd(&g_cntp[b][tid], cp);
        if (ct) atomicAdd(&g_cntt[b][tid], ct);
        if (s_obsp[tid]) g_obsp[b][tid] = 1;   // idempotent
        if (s_obst[tid]) g_obst[b][tid] = 1;
    }
    if (tid == 0) {
        float ceS = 0.f, lwpS = 0.f, lwtS = 0.f, gcS = 0.f, ppS = 0.f;
        int cecS = 0, mkS = 0;
        #pragma unroll
        for (int w = 0; w < NW; ++w) {
            ceS += r_ce[w]; lwpS += r_lwp[w]; lwtS += r_lwt[w];
            gcS += r_gc[w]; ppS += r_pp[w];
            cecS += r_cec[w]; mkS += r_mk[w];
        }
        atomicAdd(&g_ce_sum, (double)ceS);
        atomicAdd(&g_ce_cnt, cecS);
        atomicAdd(&g_lwp[b], (double)lwpS);
        atomicAdd(&g_lwt[b], (double)lwtS);
        atomicAdd(&g_maskc[b], mkS);
        atomicAdd(&g_gcs[b], (double)gcS);
        atomicAdd(&g_pps[b], (double)ppS);
    }

    // ---------- per-batch completion ticket ----------
    __threadfence();
    if (tid == 0) s_rank = atomicAdd(&g_bdone[b], 1);
    __syncthreads();
    if (s_rank != nblk - 1) return;

    // ========== per-batch epilogue (last block of this b) ==========
    __threadfence();

    if (tid < NG) { e_gsp[tid] = 0.f; e_gst[tid] = 0.f; }
    if (tid == 0) { e_sp = 0.f; e_st = 0.f; e_kl = 0.f; }
    __syncthreads();

    int gid = 0, op = 0, ot = 0;
    float ocp = 0.f, oct = 0.f;
    if (tid < NC) {
        gid = c_gid[tid];
        bool coding = (tid != 0) && (tid != 11) && (tid != 12) && (tid != 15);
        op = g_obsp[b][tid] && coding;
        ot = g_obst[b][tid] && coding;
        ocp = op ? (float)g_cntp[b][tid] : 0.f;
        oct = ot ? (float)g_cntt[b][tid] : 0.f;
        atomicAdd(&e_gsp[gid], ocp);
        atomicAdd(&e_gst[gid], oct);
    }
    __syncthreads();

    float pterm = 0.f, tterm = 0.f;
    if (tid < NC) {
        float totp = e_gsp[gid], tott = e_gst[gid];
        float ns = c_nsyn[tid];
        float rp = (op && totp > 0.f) ? ocp * ns / fmaxf(totp, 1.f) : 0.f;
        float rt = (ot && tott > 0.f) ? oct * ns / fmaxf(tott, 1.f) : 0.f;
        pterm = rp + EPS;
        int sp = species[b];
        tterm = 0.7f * rt + 0.3f * refd[sp * NC + tid] + EPS;
        atomicAdd(&e_sp, pterm);
        atomicAdd(&e_st, tterm);
    }
    __syncthreads();

    if (tid < NC) {
        float tt = tterm / e_st;
        float pp = pterm / e_sp;
        atomicAdd(&e_kl, tt * (logf(tt) - logf(pp)));
    }
    __syncthreads();

    if (tid == 0) {
        atomicAdd(&g_rscu, (double)e_kl);
        float denom = fmaxf((float)g_maskc[b], 1.f);
        float pc = expf((float)(g_lwp[b]) / denom);
        float tc = expf((float)(g_lwt[b]) / denom);
        atomicAdd(&g_cai, (double)fmaxf(tc - pc, 0.f));
        double gm = g_gcs[b] / (double)L - 0.5;
        double pm = g_pps[b] / (double)L - 0.1;
        double sd = (double)mfe[b] + 20.0;
        atomicAdd(&g_gc,  gm * gm);
        atomicAdd(&g_dyn, pm * pm);
        atomicAdd(&g_str, sd * sd);
    }
    __syncthreads();

    // self-clean this batch's scratch (values already consumed above)
    if (tid < NC) {
        g_cntp[b][tid] = 0; g_cntt[b][tid] = 0;
        g_obsp[b][tid] = 0; g_obst[b][tid] = 0;
    }
    if (tid == 0) {
        g_lwp[b] = 0.0; g_lwt[b] = 0.0;
        g_gcs[b] = 0.0; g_pps[b] = 0.0;
        g_maskc[b] = 0; g_bdone[b] = 0;
    }

    // ---------- global ticket -> final combine by last epilogue block ----------
    __threadfence();
    if (tid == 0) s_f = atomicAdd(&g_fin, 1);
    __syncthreads();
    if (s_f != B - 1) return;
    __threadfence();

    if (tid == 0) {
        double invB = 1.0 / (double)B;
        double cev = g_ce_sum / fmax((double)g_ce_cnt, 1.0);
        out[0] = (float)(cev
                       + 0.4  * g_cai  * invB
                       + 0.3  * g_rscu * invB
                       + 0.1  * g_gc   * invB
                       + 0.15 * g_str  * invB
                       + 0.1  * g_dyn  * invB);
        // reset shared scalars for next replay
        g_ce_sum = 0.0; g_ce_cnt = 0;
        g_rscu = 0.0; g_cai = 0.0; g_gc = 0.0; g_dyn = 0.0; g_str = 0.0;
        g_fin = 0;
    }
}

extern "C" void kernel_launch(void* const* d_in, const int* in_sizes, int n_in,
                              void* d_out, int out_size)
{
    const float* logits  = (const float*)d_in[0];
    const float* wmat    = (const float*)d_in[1];
    const float* refd    = (const float*)d_in[2];
    const float* gc      = (const float*)d_in[3];
    const float* mfe     = (const float*)d_in[4];
    const float* pause   = (const float*)d_in[5];
    const int*   tgt     = (const int*)d_in[6];
    const int*   aa      = (const int*)d_in[7];
    const int*   species = (const int*)d_in[8];
    const unsigned char* mask = (const unsigned char*)d_in[9];

    int B = in_sizes[4];             // mfe has B elements
    int L = in_sizes[3] / B;         // gc_pred has B*L elements

    size_t smemM = (2 * SUB * NC + NC) * sizeof(float);   // ~67 KB
    cudaFuncSetAttribute(mainK, cudaFuncAttributeMaxDynamicSharedMemorySize, (int)smemM);

    dim3 grid(L / CHUNK, B);
    mainK<<<grid, THR, smemM>>>(logits, wmat, refd, gc, pause, mfe,
                                tgt, aa, species, mask,
                                (float*)d_out, L, B);
}

// round 16
// speedup vs baseline: 1.0754x; 1.0754x over previous
#include <cuda_runtime.h>
#include <math.h>
#include <stdint.h>

#define NC 65
#define NG 22
#define MAXB 64
#define EPS 1e-8f
#define SUB 128                 // rows per subtile (one per thread)
#define NSUB 4
#define CHUNK (SUB * NSUB)      // 512 rows per block
#define THR 128
#define NW (THR / 32)
#define FULL 0xffffffffu

// ---- constants derived from AA64 = 'FFLLSSSSYY**CC*WLLLLPPPPHHQQRRRRIIIMTTTTNNKKSSRRVVVVAAAADDEEGGGG'
__constant__ int c_gid[NC] = {
    0,
    6,6, 11,11, 17,17,17,17, 21,21, 1,1, 3,3, 1, 20,
    11,11,11,11, 14,14,14,14, 8,8, 15,15, 16,16,16,16,
    9,9,9, 12, 18,18,18,18, 13,13, 10,10, 17,17, 16,16,
    19,19,19,19, 2,2,2,2, 4,4, 5,5, 7,7,7,7};
__constant__ float c_nsyn[NC] = {
    0.f,
    2,2, 6,6, 6,6,6,6, 2,2, 3,3, 2,2, 3, 1,
    6,6,6,6, 4,4,4,4, 2,2, 2,2, 6,6,6,6,
    3,3,3, 1, 4,4,4,4, 2,2, 2,2, 6,6, 6,6,
    4,4,4,4, 4,4,4,4, 2,2, 2,2, 4,4,4,4};

// ---- global scratch (zero at load; self-cleaned every run)
__device__ double g_lwp[MAXB], g_lwt[MAXB];
__device__ double g_gcs[MAXB], g_pps[MAXB];
__device__ int    g_maskc[MAXB];
__device__ int    g_cntp[MAXB][NC], g_cntt[MAXB][NC];
__device__ int    g_obsp[MAXB][NC], g_obst[MAXB][NC];
__device__ double g_ce_sum;
__device__ int    g_ce_cnt;
__device__ double g_rscu, g_cai, g_gc, g_dyn, g_str;
__device__ int    g_bdone[MAXB];
__device__ int    g_fin;

__device__ __forceinline__ void cp16(uint32_t saddr, const void* gptr) {
    asm volatile("cp.async.cg.shared.global [%0], [%1], 16;" :: "r"(saddr), "l"(gptr));
}
__device__ __forceinline__ void cp_commit() { asm volatile("cp.async.commit_group;"); }
template<int N> __device__ __forceinline__ void cp_wait() {
    asm volatile("cp.async.wait_group %0;" :: "n"(N));
}

// ------------- Single kernel: thread-per-row main pass + ticket epilogues -------------
__global__ void __launch_bounds__(THR) mainK(
    const float* __restrict__ logits, const float* __restrict__ wmat,
    const float* __restrict__ refd,
    const float* __restrict__ gc,     const float* __restrict__ pause,
    const float* __restrict__ mfe,
    const int* __restrict__ tgt,      const int* __restrict__ aa,
    const int* __restrict__ species,  const unsigned char* __restrict__ mask,
    float* __restrict__ out, int L, int B)
{
    const int b    = blockIdx.y;
    const int tid  = threadIdx.x;
    const int wid  = tid >> 5, lane = tid & 31;
    const int nblk = gridDim.x;

    extern __shared__ float smem[];
    float* s_buf  = smem;                    // 2 * SUB * NC floats (ping-pong)
    float* s_logw = smem + 2 * SUB * NC;     // NC floats

    __shared__ int   s_cntp[NC], s_cntt[NC], s_obsp[NC], s_obst[NC];
    __shared__ float r_ce[NW], r_lwp[NW], r_lwt[NW], r_gc[NW], r_pp[NW];
    __shared__ int   r_cec[NW], r_mk[NW];
    __shared__ float e_gsp[NG], e_gst[NG];
    __shared__ float e_sp, e_st, e_kl;
    __shared__ int   s_rank, s_f;

    const size_t row0 = (size_t)b * L + (size_t)blockIdx.x * CHUNK;
    const uint32_t sbase = (uint32_t)__cvta_generic_to_shared(s_buf);
    const int V = SUB * NC / 4;              // 2080 float4 per subtile

    // prefetch subtile 0
    {
        const float4* g4 = (const float4*)(logits + row0 * NC);
        for (int v = tid; v < V; v += THR) cp16(sbase + v * 16, g4 + v);
        cp_commit();
    }

    if (tid < NC) {
        int sp = __ldg(species + b);
        s_logw[tid] = __logf(fmaxf(__ldg(wmat + sp * NC + tid), EPS));
        s_cntp[tid] = 0; s_cntt[tid] = 0; s_obsp[tid] = 0; s_obst[tid] = 0;
    }

    // gc / pause partial sums: this block covers CHUNK elements of each
    {
        const float4* gp = (const float4*)(gc    + row0);
        const float4* pp = (const float4*)(pause + row0);
        float4 x = __ldg(gp + tid);
        float4 y = __ldg(pp + tid);
        float sg = x.x + x.y + x.z + x.w;
        float sp = y.x + y.y + y.z + y.w;
        #pragma unroll
        for (int o = 16; o; o >>= 1) {
            sg += __shfl_xor_sync(FULL, sg, o);
            sp += __shfl_xor_sync(FULL, sp, o);
        }
        if (lane == 0) { r_gc[wid] = sg; r_pp[wid] = sp; }
    }

    float ce_acc = 0.f, lwp_acc = 0.f, lwt_acc = 0.f;
    int   cec_acc = 0, mk_acc = 0;

    for (int s = 0; s < NSUB; ++s) {
        if (s + 1 < NSUB) {
            const float4* g4 = (const float4*)(logits + (row0 + (size_t)(s + 1) * SUB) * NC);
            uint32_t dst = sbase + ((s + 1) & 1) * (SUB * NC * 4);
            for (int v = tid; v < V; v += THR) cp16(dst + v * 16, g4 + v);
            cp_commit();
            cp_wait<1>();
        } else {
            cp_wait<0>();
        }
        __syncthreads();

        const float* row = s_buf + (s & 1) * (SUB * NC) + tid * NC;
        const size_t r = row0 + (size_t)s * SUB + tid;

        int t  = __ldg(tgt + r);
        int a  = __ldg(aa + r);
        int mk = __ldg(mask + r);

        // pass 1: max + argmax, 4 independent chains (chunks 0..15,16..31,32..47,48..64)
        float m0 = row[0],  m1 = row[16], m2 = row[32], m3 = row[48];
        int   a0 = 0,       a1 = 16,      a2 = 32,      a3 = 48;
        #pragma unroll
        for (int i = 1; i < 16; ++i) {
            float v0 = row[i];      if (v0 > m0) { m0 = v0; a0 = i; }
            float v1 = row[16 + i]; if (v1 > m1) { m1 = v1; a1 = 16 + i; }
            float v2 = row[32 + i]; if (v2 > m2) { m2 = v2; a2 = 32 + i; }
            float v3 = row[48 + i]; if (v3 > m3) { m3 = v3; a3 = 48 + i; }
        }
        { float v3 = row[64]; if (v3 > m3) { m3 = v3; a3 = 64; } }
        // combine (keep earlier chunk on ties => first-index like jnp.argmax)
        float mx; int am;
        if (m1 > m0) { mx = m1; am = a1; } else { mx = m0; am = a0; }
        if (m2 > mx) { mx = m2; am = a2; }
        if (m3 > mx) { mx = m3; am = a3; }

        // pass 2: sum of exps, 4 independent accumulators
        float e0 = 0.f, e1 = 0.f, e2 = 0.f, e3 = 0.f;
        #pragma unroll
        for (int i = 0; i < 16; ++i) {
            e0 += __expf(row[i]      - mx);
            e1 += __expf(row[16 + i] - mx);
            e2 += __expf(row[32 + i] - mx);
            e3 += __expf(row[48 + i] - mx);
        }
        e3 += __expf(row[64] - mx);
        float e = (e0 + e1) + (e2 + e3);

        float nll = mx + __logf(e) - row[t];

        if (t != 0) { ce_acc += nll; cec_acc++; }
        if (mk) {
            mk_acc++;
            lwp_acc += s_logw[am];
            lwt_acc += s_logw[t];
            if (am > 0) { atomicAdd(&s_cntp[am], 1); if (a > 2) s_obsp[am] = 1; }
            if (t  > 0) { atomicAdd(&s_cntt[t], 1);  if (a > 2) s_obst[t]  = 1; }
        }
        __syncthreads();   // done reading this buffer before it is refilled
    }

    // block reduction of scalar accumulators
    #pragma unroll
    for (int o = 16; o; o >>= 1) {
        ce_acc  += __shfl_xor_sync(FULL, ce_acc,  o);
        lwp_acc += __shfl_xor_sync(FULL, lwp_acc, o);
        lwt_acc += __shfl_xor_sync(FULL, lwt_acc, o);
        cec_acc += __shfl_xor_sync(FULL, cec_acc, o);
        mk_acc  += __shfl_xor_sync(FULL, mk_acc,  o);
    }
    if (lane == 0) {
        r_ce[wid] = ce_acc; r_lwp[wid] = lwp_acc; r_lwt[wid] = lwt_acc;
        r_cec[wid] = cec_acc; r_mk[wid] = mk_acc;
    }
    __syncthreads();

    if (tid < NC) {
        int cp = s_cntp[tid], ct = s_cntt[tid];
        if (cp) atomicAdd(&g_cntp[b][tid], cp);
        if (ct) atomicAdd(&g_cntt[b][tid], ct);
        if (s_obsp[tid]) g_obsp[b][tid] = 1;   // idempotent
        if (s_obst[tid]) g_obst[b][tid] = 1;
    }
    if (tid == 0) {
        float ceS = 0.f, lwpS = 0.f, lwtS = 0.f, gcS = 0.f, ppS = 0.f;
        int cecS = 0, mkS = 0;
        #pragma unroll
        for (int w = 0; w < NW; ++w) {
            ceS += r_ce[w]; lwpS += r_lwp[w]; lwtS += r_lwt[w];
            gcS += r_gc[w]; ppS += r_pp[w];
            cecS += r_cec[w]; mkS += r_mk[w];
        }
        atomicAdd(&g_ce_sum, (double)ceS);
        atomicAdd(&g_ce_cnt, cecS);
        atomicAdd(&g_lwp[b], (double)lwpS);
        atomicAdd(&g_lwt[b], (double)lwtS);
        atomicAdd(&g_maskc[b], mkS);
        atomicAdd(&g_gcs[b], (double)gcS);
        atomicAdd(&g_pps[b], (double)ppS);
    }

    // ---------- per-batch completion ticket ----------
    __threadfence();
    if (tid == 0) s_rank = atomicAdd(&g_bdone[b], 1);
    __syncthreads();
    if (s_rank != nblk - 1) return;

    // ========== per-batch epilogue (last block of this b) ==========
    __threadfence();

    if (tid < NG) { e_gsp[tid] = 0.f; e_gst[tid] = 0.f; }
    if (tid == 0) { e_sp = 0.f; e_st = 0.f; e_kl = 0.f; }
    __syncthreads();

    int gid = 0, op = 0, ot = 0;
    float ocp = 0.f, oct = 0.f;
    if (tid < NC) {
        gid = c_gid[tid];
        bool coding = (tid != 0) && (tid != 11) && (tid != 12) && (tid != 15);
        op = g_obsp[b][tid] && coding;
        ot = g_obst[b][tid] && coding;
        ocp = op ? (float)g_cntp[b][tid] : 0.f;
        oct = ot ? (float)g_cntt[b][tid] : 0.f;
        atomicAdd(&e_gsp[gid], ocp);
        atomicAdd(&e_gst[gid], oct);
    }
    __syncthreads();

    float pterm = 0.f, tterm = 0.f;
    if (tid < NC) {
        float totp = e_gsp[gid], tott = e_gst[gid];
        float ns = c_nsyn[tid];
        float rp = (op && totp > 0.f) ? ocp * ns / fmaxf(totp, 1.f) : 0.f;
        float rt = (ot && tott > 0.f) ? oct * ns / fmaxf(tott, 1.f) : 0.f;
        pterm = rp + EPS;
        int sp = species[b];
        tterm = 0.7f * rt + 0.3f * refd[sp * NC + tid] + EPS;
        atomicAdd(&e_sp, pterm);
        atomicAdd(&e_st, tterm);
    }
    __syncthreads();

    if (tid < NC) {
        float tt = tterm / e_st;
        float pp = pterm / e_sp;
        atomicAdd(&e_kl, tt * (logf(tt) - logf(pp)));
    }
    __syncthreads();

    if (tid == 0) {
        atomicAdd(&g_rscu, (double)e_kl);
        float denom = fmaxf((float)g_maskc[b], 1.f);
        float pc = expf((float)(g_lwp[b]) / denom);
        float tc = expf((float)(g_lwt[b]) / denom);
        atomicAdd(&g_cai, (double)fmaxf(tc - pc, 0.f));
        double gm = g_gcs[b] / (double)L - 0.5;
        double pm = g_pps[b] / (double)L - 0.1;
        double sd = (double)mfe[b] + 20.0;
        atomicAdd(&g_gc,  gm * gm);
        atomicAdd(&g_dyn, pm * pm);
        atomicAdd(&g_str, sd * sd);
    }
    __syncthreads();

    // self-clean this batch's scratch (values already consumed above)
    if (tid < NC) {
        g_cntp[b][tid] = 0; g_cntt[b][tid] = 0;
        g_obsp[b][tid] = 0; g_obst[b][tid] = 0;
    }
    if (tid == 0) {
        g_lwp[b] = 0.0; g_lwt[b] = 0.0;
        g_gcs[b] = 0.0; g_pps[b] = 0.0;
        g_maskc[b] = 0; g_bdone[b] = 0;
    }

    // ---------- global ticket -> final combine by last epilogue block ----------
    __threadfence();
    if (tid == 0) s_f = atomicAdd(&g_fin, 1);
    __syncthreads();
    if (s_f != B - 1) return;
    __threadfence();

    if (tid == 0) {
        double invB = 1.0 / (double)B;
        double cev = g_ce_sum / fmax((double)g_ce_cnt, 1.0);
        out[0] = (float)(cev
                       + 0.4  * g_cai  * invB
                       + 0.3  * g_rscu * invB
                       + 0.1  * g_gc   * invB
                       + 0.15 * g_str  * invB
                       + 0.1  * g_dyn  * invB);
        // reset shared scalars for next replay
        g_ce_sum = 0.0; g_ce_cnt = 0;
        g_rscu = 0.0; g_cai = 0.0; g_gc = 0.0; g_dyn = 0.0; g_str = 0.0;
        g_fin = 0;
    }
}

extern "C" void kernel_launch(void* const* d_in, const int* in_sizes, int n_in,
                              void* d_out, int out_size)
{
    const float* logits  = (const float*)d_in[0];
    const float* wmat    = (const float*)d_in[1];
    const float* refd    = (const float*)d_in[2];
    const float* gc      = (const float*)d_in[3];
    const float* mfe     = (const float*)d_in[4];
    const float* pause   = (const float*)d_in[5];
    const int*   tgt     = (const int*)d_in[6];
    const int*   aa      = (const int*)d_in[7];
    const int*   species = (const int*)d_in[8];
    const unsigned char* mask = (const unsigned char*)d_in[9];

    int B = in_sizes[4];             // mfe has B elements
    int L = in_sizes[3] / B;         // gc_pred has B*L elements

    size_t smemM = (2 * SUB * NC + NC) * sizeof(float);   // ~67 KB
    cudaFuncSetAttribute(mainK, cudaFuncAttributeMaxDynamicSharedMemorySize, (int)smemM);

    dim3 grid(L / CHUNK, B);
    mainK<<<grid, THR, smemM>>>(logits, wmat, refd, gc, pause, mfe,
                                tgt, aa, species, mask,
                                (float*)d_out, L, B);
}

// round 17
// speedup vs baseline: 1.3178x; 1.2255x over previous
#include <cuda_runtime.h>
#include <math.h>
#include <stdint.h>

#define NC 65
#define NG 22
#define MAXB 64
#define EPS 1e-8f
#define THR 256
#define RPT 4                     // rows per thread
#define ROWS_BLK (THR * RPT)      // 1024 rows per block
#define NW (THR / 32)
#define FULL 0xffffffffu

// ---- constants derived from AA64 = 'FFLLSSSSYY**CC*WLLLLPPPPHHQQRRRRIIIMTTTTNNKKSSRRVVVVAAAADDEEGGGG'
__constant__ int c_gid[NC] = {
    0,
    6,6, 11,11, 17,17,17,17, 21,21, 1,1, 3,3, 1, 20,
    11,11,11,11, 14,14,14,14, 8,8, 15,15, 16,16,16,16,
    9,9,9, 12, 18,18,18,18, 13,13, 10,10, 17,17, 16,16,
    19,19,19,19, 2,2,2,2, 4,4, 5,5, 7,7,7,7};
__constant__ float c_nsyn[NC] = {
    0.f,
    2,2, 6,6, 6,6,6,6, 2,2, 3,3, 2,2, 3, 1,
    6,6,6,6, 4,4,4,4, 2,2, 2,2, 6,6,6,6,
    3,3,3, 1, 4,4,4,4, 2,2, 2,2, 6,6, 6,6,
    4,4,4,4, 4,4,4,4, 2,2, 2,2, 4,4,4,4};

// ---- global scratch (zero at load; self-cleaned every run)
__device__ double g_lwp[MAXB], g_lwt[MAXB];
__device__ double g_gcs[MAXB], g_pps[MAXB];
__device__ int    g_maskc[MAXB];
__device__ int    g_cntp[MAXB][NC], g_cntt[MAXB][NC];
__device__ int    g_obsp[MAXB][NC], g_obst[MAXB][NC];
__device__ double g_ce_sum;
__device__ int    g_ce_cnt;
__device__ double g_rscu, g_cai, g_gc, g_dyn, g_str;
__device__ int    g_bdone[MAXB];
__device__ int    g_fin;

// ------------- Single kernel: direct-global online softmax + ticket epilogues -------------
__global__ void __launch_bounds__(THR, 3) mainK(
    const float* __restrict__ logits, const float* __restrict__ wmat,
    const float* __restrict__ refd,
    const float* __restrict__ gc,     const float* __restrict__ pause,
    const float* __restrict__ mfe,
    const int* __restrict__ tgt,      const int* __restrict__ aa,
    const int* __restrict__ species,  const unsigned char* __restrict__ mask,
    float* __restrict__ out, int L, int B)
{
    const int b    = blockIdx.y;
    const int tid  = threadIdx.x;
    const int wid  = tid >> 5, lane = tid & 31;
    const int nblk = gridDim.x;

    __shared__ float s_logw[NC];
    __shared__ int   s_cntp[NC], s_cntt[NC], s_obsp[NC], s_obst[NC];
    __shared__ float r_ce[NW], r_lwp[NW], r_lwt[NW], r_gc[NW], r_pp[NW];
    __shared__ int   r_cec[NW], r_mk[NW];
    __shared__ float e_gsp[NG], e_gst[NG];
    __shared__ float e_sp, e_st, e_kl;
    __shared__ int   s_rank, s_f;

    if (tid < NC) {
        int sp = __ldg(species + b);
        s_logw[tid] = __logf(fmaxf(__ldg(wmat + sp * NC + tid), EPS));
        s_cntp[tid] = 0; s_cntt[tid] = 0; s_obsp[tid] = 0; s_obst[tid] = 0;
    }

    const size_t row0 = (size_t)b * L + (size_t)blockIdx.x * ROWS_BLK;

    // gc / pause partial sums: block covers ROWS_BLK elements of each
    {
        const float4* gp = (const float4*)(gc    + row0);
        const float4* pp = (const float4*)(pause + row0);
        float4 x = __ldg(gp + tid);
        float4 y = __ldg(pp + tid);
        float sg = x.x + x.y + x.z + x.w;
        float sp = y.x + y.y + y.z + y.w;
        #pragma unroll
        for (int o = 16; o; o >>= 1) {
            sg += __shfl_xor_sync(FULL, sg, o);
            sp += __shfl_xor_sync(FULL, sp, o);
        }
        if (lane == 0) { r_gc[wid] = sg; r_pp[wid] = sp; }
    }
    __syncthreads();   // s_logw / s_cnt* ready

    // ---- main: 4 consecutive rows per thread = 65 contiguous float4 ----
    const size_t rbase = row0 + (size_t)tid * RPT;       // first of this thread's 4 rows
    const float4* p4 = (const float4*)(logits + rbase * NC);

    float mx[RPT], sm[RPT];
    int   am[RPT];
    #pragma unroll
    for (int rr = 0; rr < RPT; ++rr) { mx[rr] = -INFINITY; sm[rr] = 0.f; am[rr] = 0; }

    #pragma unroll
    for (int k = 0; k < 65; ++k) {
        float4 f = __ldg(p4 + k);
        #pragma unroll
        for (int m = 0; m < 4; ++m) {
            const int e  = 4 * k + m;
            const int rr = e / NC;          // compile-time
            const int cc = e - rr * NC;     // compile-time
            float v  = (&f.x)[m];
            float mo = mx[rr];
            float mn = fmaxf(mo, v);
            if (v > mo) am[rr] = cc;        // ascending cc + strict > => first index
            sm[rr] = sm[rr] * __expf(mo - mn) + __expf(v - mn);
            mx[rr] = mn;
        }
    }

    // side data for the 4 rows (16B / 4B aligned vector loads)
    int4  t4 = __ldg((const int4*)(tgt + rbase));
    int4  a4 = __ldg((const int4*)(aa  + rbase));
    uchar4 m4 = __ldg((const uchar4*)(mask + rbase));

    float ce_acc = 0.f, lwp_acc = 0.f, lwt_acc = 0.f;
    int   cec_acc = 0, mk_acc = 0;

    #pragma unroll
    for (int rr = 0; rr < RPT; ++rr) {
        int t  = (&t4.x)[rr];
        int a  = (&a4.x)[rr];
        int mk = (rr == 0) ? m4.x : (rr == 1) ? m4.y : (rr == 2) ? m4.z : m4.w;

        float tl  = __ldg(logits + (rbase + rr) * NC + t);
        float nll = mx[rr] + __logf(sm[rr]) - tl;

        if (t != 0) { ce_acc += nll; cec_acc++; }
        if (mk) {
            mk_acc++;
            lwp_acc += s_logw[am[rr]];
            lwt_acc += s_logw[t];
            if (am[rr] > 0) { atomicAdd(&s_cntp[am[rr]], 1); if (a > 2) s_obsp[am[rr]] = 1; }
            if (t      > 0) { atomicAdd(&s_cntt[t], 1);      if (a > 2) s_obst[t]      = 1; }
        }
    }

    // block reduction of scalar accumulators
    #pragma unroll
    for (int o = 16; o; o >>= 1) {
        ce_acc  += __shfl_xor_sync(FULL, ce_acc,  o);
        lwp_acc += __shfl_xor_sync(FULL, lwp_acc, o);
        lwt_acc += __shfl_xor_sync(FULL, lwt_acc, o);
        cec_acc += __shfl_xor_sync(FULL, cec_acc, o);
        mk_acc  += __shfl_xor_sync(FULL, mk_acc,  o);
    }
    if (lane == 0) {
        r_ce[wid] = ce_acc; r_lwp[wid] = lwp_acc; r_lwt[wid] = lwt_acc;
        r_cec[wid] = cec_acc; r_mk[wid] = mk_acc;
    }
    __syncthreads();

    if (tid < NC) {
        int cp = s_cntp[tid], ct = s_cntt[tid];
        if (cp) atomicAdd(&g_cntp[b][tid], cp);
        if (ct) atomicAdd(&g_cntt[b][tid], ct);
        if (s_obsp[tid]) g_obsp[b][tid] = 1;   // idempotent
        if (s_obst[tid]) g_obst[b][tid] = 1;
    }
    if (tid == 0) {
        float ceS = 0.f, lwpS = 0.f, lwtS = 0.f, gcS = 0.f, ppS = 0.f;
        int cecS = 0, mkS = 0;
        #pragma unroll
        for (int w = 0; w < NW; ++w) {
            ceS += r_ce[w]; lwpS += r_lwp[w]; lwtS += r_lwt[w];
            gcS += r_gc[w]; ppS += r_pp[w];
            cecS += r_cec[w]; mkS += r_mk[w];
        }
        atomicAdd(&g_ce_sum, (double)ceS);
        atomicAdd(&g_ce_cnt, cecS);
        atomicAdd(&g_lwp[b], (double)lwpS);
        atomicAdd(&g_lwt[b], (double)lwtS);
        atomicAdd(&g_maskc[b], mkS);
        atomicAdd(&g_gcs[b], (double)gcS);
        atomicAdd(&g_pps[b], (double)ppS);
    }

    // ---------- per-batch completion ticket ----------
    __threadfence();
    if (tid == 0) s_rank = atomicAdd(&g_bdone[b], 1);
    __syncthreads();
    if (s_rank != nblk - 1) return;

    // ========== per-batch epilogue (last block of this b) ==========
    __threadfence();

    if (tid < NG) { e_gsp[tid] = 0.f; e_gst[tid] = 0.f; }
    if (tid == 0) { e_sp = 0.f; e_st = 0.f; e_kl = 0.f; }
    __syncthreads();

    int gid = 0, op = 0, ot = 0;
    float ocp = 0.f, oct = 0.f;
    if (tid < NC) {
        gid = c_gid[tid];
        bool coding = (tid != 0) && (tid != 11) && (tid != 12) && (tid != 15);
        op = g_obsp[b][tid] && coding;
        ot = g_obst[b][tid] && coding;
        ocp = op ? (float)g_cntp[b][tid] : 0.f;
        oct = ot ? (float)g_cntt[b][tid] : 0.f;
        atomicAdd(&e_gsp[gid], ocp);
        atomicAdd(&e_gst[gid], oct);
    }
    __syncthreads();

    float pterm = 0.f, tterm = 0.f;
    if (tid < NC) {
        float totp = e_gsp[gid], tott = e_gst[gid];
        float ns = c_nsyn[tid];
        float rp = (op && totp > 0.f) ? ocp * ns / fmaxf(totp, 1.f) : 0.f;
        float rt = (ot && tott > 0.f) ? oct * ns / fmaxf(tott, 1.f) : 0.f;
        pterm = rp + EPS;
        int sp = species[b];
        tterm = 0.7f * rt + 0.3f * refd[sp * NC + tid] + EPS;
        atomicAdd(&e_sp, pterm);
        atomicAdd(&e_st, tterm);
    }
    __syncthreads();

    if (tid < NC) {
        float tt = tterm / e_st;
        float pp = pterm / e_sp;
        atomicAdd(&e_kl, tt * (logf(tt) - logf(pp)));
    }
    __syncthreads();

    if (tid == 0) {
        atomicAdd(&g_rscu, (double)e_kl);
        float denom = fmaxf((float)g_maskc[b], 1.f);
        float pc = expf((float)(g_lwp[b]) / denom);
        float tc = expf((float)(g_lwt[b]) / denom);
        atomicAdd(&g_cai, (double)fmaxf(tc - pc, 0.f));
        double gm = g_gcs[b] / (double)L - 0.5;
        double pm = g_pps[b] / (double)L - 0.1;
        double sd = (double)mfe[b] + 20.0;
        atomicAdd(&g_gc,  gm * gm);
        atomicAdd(&g_dyn, pm * pm);
        atomicAdd(&g_str, sd * sd);
    }
    __syncthreads();

    // self-clean this batch's scratch (values already consumed above)
    if (tid < NC) {
        g_cntp[b][tid] = 0; g_cntt[b][tid] = 0;
        g_obsp[b][tid] = 0; g_obst[b][tid] = 0;
    }
    if (tid == 0) {
        g_lwp[b] = 0.0; g_lwt[b] = 0.0;
        g_gcs[b] = 0.0; g_pps[b] = 0.0;
        g_maskc[b] = 0; g_bdone[b] = 0;
    }

    // ---------- global ticket -> final combine by last epilogue block ----------
    __threadfence();
    if (tid == 0) s_f = atomicAdd(&g_fin, 1);
    __syncthreads();
    if (s_f != B - 1) return;
    __threadfence();

    if (tid == 0) {
        double invB = 1.0 / (double)B;
        double cev = g_ce_sum / fmax((double)g_ce_cnt, 1.0);
        out[0] = (float)(cev
                       + 0.4  * g_cai  * invB
                       + 0.3  * g_rscu * invB
                       + 0.1  * g_gc   * invB
                       + 0.15 * g_str  * invB
                       + 0.1  * g_dyn  * invB);
        // reset shared scalars for next replay
        g_ce_sum = 0.0; g_ce_cnt = 0;
        g_rscu = 0.0; g_cai = 0.0; g_gc = 0.0; g_dyn = 0.0; g_str = 0.0;
        g_fin = 0;
    }
}

extern "C" void kernel_launch(void* const* d_in, const int* in_sizes, int n_in,
                              void* d_out, int out_size)
{
    const float* logits  = (const float*)d_in[0];
    const float* wmat    = (const float*)d_in[1];
    const float* refd    = (const float*)d_in[2];
    const float* gc      = (const float*)d_in[3];
    const float* mfe     = (const float*)d_in[4];
    const float* pause   = (const float*)d_in[5];
    const int*   tgt     = (const int*)d_in[6];
    const int*   aa      = (const int*)d_in[7];
    const int*   species = (const int*)d_in[8];
    const unsigned char* mask = (const unsigned char*)d_in[9];

    int B = in_sizes[4];             // mfe has B elements
    int L = in_sizes[3] / B;         // gc_pred has B*L elements

    dim3 grid(L / ROWS_BLK, B);      // 8 x 64 = 512 blocks, single wave
    mainK<<<grid, THR>>>(logits, wmat, refd, gc, pause, mfe,
                         tgt, aa, species, mask,
                         (float*)d_out, L, B);
}